// round 9
// baseline (speedup 1.0000x reference)
#include <cuda_runtime.h>
#include <math.h>

// SBEceLoss: logits [N,100] f32, labels [N] i64 -> scalar ece (f32)
// Single fused kernel: warp-per-row, 4 rows/iter.
//   - per row: 1 REDUX + 1 ballot; the winner LANE issues a predicated
//     shared atomic directly (no ffs/shfl broadcast, no divergent block)
//   - certification (acc==0 proof for all 4 rows) = 1 ballot + 2 compares
//   - per-block shared histogram -> global REDs
//   - last block computes 100x15 bin softmax + ECE, resets device state.

#define C_CLASSES 100
#define NB 15
#define RPI 4
#define FULLM 0xffffffffu
#define REALM 0x01ffffffu   // lanes 0..24 (distinct columns only)

__device__ int g_cnt[C_CLASSES];
__device__ int g_acc[C_CLASSES];
__device__ unsigned g_done;

// Order-preserving float->uint encoding (and inverse).
__device__ __forceinline__ unsigned fenc(float f) {
    unsigned u = __float_as_uint(f);
    return u ^ ((unsigned)((int)u >> 31) | 0x80000000u);
}
__device__ __forceinline__ float fdec(unsigned e) {
    unsigned mask = (~(unsigned)((int)e >> 31)) | 0x80000000u;
    return __uint_as_float(e ^ mask);
}

__global__ void __launch_bounds__(256)
fused_kernel(const float* __restrict__ logits,
             const long long* __restrict__ labels,
             int n_rows, float* __restrict__ out) {
    __shared__ int  s_cnt[C_CLASSES];
    __shared__ int  s_acc[C_CLASSES];
    __shared__ bool s_last;
    for (int i = threadIdx.x; i < C_CLASSES; i += blockDim.x) { s_cnt[i] = 0; s_acc[i] = 0; }
    __syncthreads();

    const int lane  = threadIdx.x & 31;
    const int gw    = blockIdx.x * (blockDim.x >> 5) + (threadIdx.x >> 5);
    const int warps = gridDim.x * (blockDim.x >> 5);
    const unsigned lt_mask = (1u << lane) - 1u;
    const float NEG = __int_as_float(0xff800000);

    // lanes 25..31 mirror lanes 0..6: identical addresses coalesce (no extra
    // traffic); identical keys leave REDUX/ballot results unchanged; the
    // mirrored lanes can never be "first tie" (a lower lane always ties them),
    // so they never commit atomics. REALM masks them from distinct counts.
    const int c4 = (lane < 25) ? lane : (lane - 25);

    const int rows_per_sweep = warps * RPI;
    const int sweeps = n_rows / rows_per_sweep;      // 8 exact for N=2^19
    const int main_rows = sweeps * rows_per_sweep;

    const unsigned KEY_HI = fenc(8.0f);    // k1 <  KEY_HI => mg <  8
    const unsigned KEY_LO = fenc(-16.0f);  // k1 >  KEY_LO => mg > -16

    const float4* p = reinterpret_cast<const float4*>(logits) + (size_t)gw * RPI * 25 + c4;
    int rowbase = gw * RPI;

    for (int s = 0; s < sweeps; ++s) {
        float4 v[RPI];
        #pragma unroll
        for (int r = 0; r < RPI; r++) v[r] = __ldg(p + r * 25);   // MLP=4/warp

        float    m_min  = __int_as_float(0x7f800000);   // +inf
        unsigned k1_max = 0u, k1_min = FULLM;

        #pragma unroll
        for (int r = 0; r < RPI; r++) {
            // lane max (fma pipe) + first-occurrence local column
            float m = fmaxf(fmaxf(v[r].x, v[r].y), fmaxf(v[r].z, v[r].w));
            int j = c4 * 4 + ((m == v[r].x) ? 0 : ((m == v[r].y) ? 1 : ((m == v[r].z) ? 2 : 3)));

            unsigned em  = fenc(m);                       // exact
            unsigned k1  = __reduce_max_sync(FULLM, em);
            unsigned bal = __ballot_sync(FULLM, em == k1);
            // winner lane = lowest tied lane = first-occurrence argmax;
            // it commits its own count (predicated single atomic, no broadcast)
            if ((em == k1) && ((bal & lt_mask) == 0u))
                atomicAdd(&s_cnt[j], 1);

            m_min  = fminf(m_min, m);
            k1_max = max(k1_max, k1);
            k1_min = min(k1_min, k1);
        }

        // One vote certifies acc==0 for all 4 rows (exact):
        //   >=2 DISTINCT lanes whose min-over-rows lane-max > -4, and every
        //   row max in (-16, 8)  =>  per row a 2nd element > -4 > mg-12 and
        //   |mg| < 16  =>  log(sumexp) >= log(1+e^-12) = 6.1e-6 > ulp(8)/2
        //   =>  max logprob strictly < 0  =>  never equals an integer label.
        unsigned cbal = __ballot_sync(FULLM, m_min > -4.0f) & REALM;
        bool all_good = (__popc(cbal) >= 2) && (k1_max < KEY_HI) && (k1_min > KEY_LO);

        if (!all_good) {   // rare exact path (recompute per row)
            #pragma unroll
            for (int r = 0; r < RPI; r++) {
                float m = fmaxf(fmaxf(v[r].x, v[r].y), fmaxf(v[r].z, v[r].w));
                int j = c4 * 4 + ((m == v[r].x) ? 0 : ((m == v[r].y) ? 1 : ((m == v[r].z) ? 2 : 3)));
                unsigned em  = fenc(m);
                unsigned k1  = __reduce_max_sync(FULLM, em);
                unsigned bal = __ballot_sync(FULLM, em == k1);
                float mg = fdec(k1);
                unsigned b = __ballot_sync(FULLM, m > (mg - 12.0f)) & REALM;
                if ((__popc(b) >= 2) && (fabsf(mg) < 16.0f)) continue;  // acc=0 proven
                float sv = 0.0f;
                if (lane < 25)
                    sv = expf(v[r].x - mg) + expf(v[r].y - mg) +
                         expf(v[r].z - mg) + expf(v[r].w - mg);
                #pragma unroll
                for (int off = 16; off; off >>= 1)
                    sv += __shfl_xor_sync(FULLM, sv, off);
                float pred = mg - (mg + logf(sv));       // uniform across lanes
                bool acc = (pred == (float)labels[rowbase + r]);
                if (acc && (em == k1) && ((bal & lt_mask) == 0u))
                    atomicAdd(&s_acc[j], 1);             // winner lane only
            }
        }

        p += (size_t)warps * RPI * 25;
        rowbase += rows_per_sweep;
    }

    // ---- generic tail (empty for N=2^19 with this launch config) ----
    for (int row = main_rows + gw; row < n_rows; row += warps) {
        float4 vr = (lane < 25)
            ? __ldg(reinterpret_cast<const float4*>(logits + (size_t)row * C_CLASSES) + lane)
            : make_float4(NEG, NEG, NEG, NEG);
        float m = fmaxf(fmaxf(vr.x, vr.y), fmaxf(vr.z, vr.w));
        int j = c4 * 4 + ((m == vr.x) ? 0 : ((m == vr.y) ? 1 : ((m == vr.z) ? 2 : 3)));
        unsigned em  = fenc(m);
        unsigned k1  = __reduce_max_sync(FULLM, em);
        unsigned bal = __ballot_sync(FULLM, em == k1);
        bool iswin = (em == k1) && (lane < 25) && ((bal & lt_mask) == 0u);
        float mg = fdec(k1);
        unsigned b = __ballot_sync(FULLM, m > (mg - 12.0f)) & REALM;
        int acc = 0;
        if (!((__popc(b) >= 2) && (fabsf(mg) < 16.0f))) {
            float sv = 0.0f;
            if (lane < 25)
                sv = expf(vr.x - mg) + expf(vr.y - mg) + expf(vr.z - mg) + expf(vr.w - mg);
            #pragma unroll
            for (int off = 16; off; off >>= 1) sv += __shfl_xor_sync(FULLM, sv, off);
            float pred = mg - (mg + logf(sv));
            acc = (pred == (float)labels[row]) ? 1 : 0;
        }
        if (iswin) {
            atomicAdd(&s_cnt[j], 1);
            if (acc) atomicAdd(&s_acc[j], 1);
        }
    }

    // ---- flush block histogram to global ----
    __syncthreads();
    for (int i = threadIdx.x; i < C_CLASSES; i += blockDim.x) {
        int c = s_cnt[i]; if (c) atomicAdd(&g_cnt[i], c);
        int a = s_acc[i]; if (a) atomicAdd(&g_acc[i], a);
    }
    __threadfence();
    __syncthreads();

    if (threadIdx.x == 0) {
        unsigned rank = atomicAdd(&g_done, 1u);
        s_last = (rank == gridDim.x - 1);
    }
    __syncthreads();
    if (!s_last) return;

    // ================= finalize (last block only) =================
    __shared__ float s_coef[C_CLASSES][NB + 1];
    __shared__ int   s_c2[C_CLASSES];
    __shared__ int   s_a2[C_CLASSES];
    __shared__ float s_sum[NB], s_conf[NB], s_accs[NB];

    int t = threadIdx.x;
    if (t < C_CLASSES) {
        int cnt = __ldcg(&g_cnt[t]);
        int ac  = __ldcg(&g_acc[t]);
        s_c2[t] = cnt;
        s_a2[t] = ac;
        float cf = (float)t;
        float d[NB];
        float dmax = __int_as_float(0xff800000);
        #pragma unroll
        for (int jj = 0; jj < NB; jj++) {
            float aj = (float)((2 * jj + 1) / 30.0);
            float tt = cf - aj;
            d[jj] = -(tt * tt) / 0.01f;
            dmax = fmaxf(dmax, d[jj]);
        }
        float denom = 0.0f;
        #pragma unroll
        for (int jj = 0; jj < NB; jj++) denom += expf(d[jj] - dmax);
        #pragma unroll
        for (int jj = 0; jj < NB; jj++) s_coef[t][jj] = expf(d[jj] - dmax) / denom;
        g_cnt[t] = 0;     // reset for next graph replay
        g_acc[t] = 0;
    }
    if (t == 0) g_done = 0;
    __syncthreads();

    if (t < NB) {
        float sum_c = 0.0f, sum_cc = 0.0f, sum_a = 0.0f;
        for (int c = 0; c < C_CLASSES; c++) {
            int cnt = s_c2[c];
            int ac  = s_a2[c];
            if ((cnt | ac) == 0) continue;
            float coeff = s_coef[c][t];
            float fcnt  = (float)cnt;   // exact: cnt < 2^24
            float cf    = (float)c;
            sum_c  += fcnt * coeff;
            sum_cc += fcnt * cf * coeff;
            sum_a  += (float)ac * coeff;
        }
        s_sum[t]  = sum_c;
        s_conf[t] = sum_cc;
        s_accs[t] = sum_a;
    }
    __syncthreads();

    if (t == 0) {
        float tot = 0.0f;
        #pragma unroll
        for (int jj = 0; jj < NB; jj++) tot += fabsf(s_sum[jj]);
        float wden = fmaxf(tot, 1e-5f);
        float acc2 = 0.0f;
        #pragma unroll
        for (int jj = 0; jj < NB; jj++) {
            float den = fmaxf(s_sum[jj], 1e-5f);
            float bc  = s_conf[jj] / den;
            float ba  = s_accs[jj] / den;
            float w   = s_sum[jj] / wden;
            float df  = bc - ba;
            acc2 += df * df * w;
        }
        out[0] = sqrtf(acc2);
    }
}

extern "C" void kernel_launch(void* const* d_in, const int* in_sizes, int n_in,
                              void* d_out, int out_size) {
    const float*     logits = (const float*)d_in[0];
    const long long* labels = (const long long*)d_in[1];
    float*           out    = (float*)d_out;
    int n_rows = in_sizes[1];  // labels count = N

    // 2048 blocks * 8 warps * 4 rows = 65536 rows/sweep; 2^19/2^16 = 8 exact sweeps
    fused_kernel<<<2048, 256>>>(logits, labels, n_rows, out);
}

// round 10
// speedup vs baseline: 1.2498x; 1.2498x over previous
#include <cuda_runtime.h>
#include <math.h>

// SBEceLoss: logits [N,100] f32, labels [N] i64 -> scalar ece (f32)
// Thread-per-row with cp.async SMEM staging (no per-row warp collectives):
//   - 32-row tiles (12.8KB) double-buffered via cp.async.cg (16B, coalesced)
//   - thread t reduces quarter-row (25 floats) from SMEM (conflict-free),
//     2 shfl_xor rounds merge the 4 quarters -> exact first-occurrence argmax
//   - certification (acc==0 proof) is thread-local: cnt(>-4)>=2 && -16<m<8
//   - per-block shared histogram -> global REDs
//   - last block computes 100x15 bin softmax + ECE (aliasing the tile SMEM),
//     writes out[0], resets device state for the next graph replay.

#define C_CLASSES 100
#define NB 15
#define TILE_ROWS 32
#define TILE_FLOATS (TILE_ROWS * C_CLASSES)   // 3200
#define TILE_BYTES  (TILE_FLOATS * 4)         // 12800 (128B-aligned tiles)
#define THREADS 128
#define FULLM 0xffffffffu

__device__ int g_cnt[C_CLASSES];
__device__ int g_acc[C_CLASSES];
__device__ unsigned g_done;

__device__ __forceinline__ void cp_async16(unsigned saddr, const void* gaddr) {
    asm volatile("cp.async.cg.shared.global [%0], [%1], 16;" :: "r"(saddr), "l"(gaddr));
}
__device__ __forceinline__ void cp_commit() {
    asm volatile("cp.async.commit_group;" ::: "memory");
}

__global__ void __launch_bounds__(THREADS)
fused_kernel(const float* __restrict__ logits,
             const long long* __restrict__ labels,
             int n_rows, float* __restrict__ out) {
    __shared__ __align__(16) float sbuf[2][TILE_FLOATS];   // 25.6 KB
    __shared__ int  s_cnt[C_CLASSES];
    __shared__ int  s_acc[C_CLASSES];
    __shared__ bool s_last;

    const int tid = threadIdx.x;
    for (int i = tid; i < C_CLASSES; i += THREADS) { s_cnt[i] = 0; s_acc[i] = 0; }

    const int tiles = (n_rows + TILE_ROWS - 1) / TILE_ROWS;
    const unsigned sb[2] = {
        (unsigned)__cvta_generic_to_shared(&sbuf[0][0]),
        (unsigned)__cvta_generic_to_shared(&sbuf[1][0])
    };

    // ---- prologue prefetch (tile = blockIdx.x into buffer 0) ----
    int tile = blockIdx.x;
    if (tile < tiles) {
        const char* g = (const char*)logits + (size_t)tile * TILE_BYTES;
        int valid = min(TILE_ROWS, n_rows - tile * TILE_ROWS) * 400;
        #pragma unroll
        for (int k = 0; k < 7; k++) {
            int off = (tid + k * THREADS) * 16;
            if (off < TILE_BYTES && off < valid) cp_async16(sb[0] + off, g + off);
        }
    }
    cp_commit();

    const int q = tid & 3;               // quarter within the row
    int b = 0;
    for (; tile < tiles; tile += gridDim.x, b ^= 1) {
        // issue next tile into the other buffer (overlaps current processing)
        int next = tile + gridDim.x;
        if (next < tiles) {
            const char* g = (const char*)logits + (size_t)next * TILE_BYTES;
            int valid = min(TILE_ROWS, n_rows - next * TILE_ROWS) * 400;
            unsigned sdst = sb[b ^ 1];
            #pragma unroll
            for (int k = 0; k < 7; k++) {
                int off = (tid + k * THREADS) * 16;
                if (off < TILE_BYTES && off < valid) cp_async16(sdst + off, g + off);
            }
        }
        cp_commit();
        asm volatile("cp.async.wait_group 1;" ::: "memory");  // current tile ready
        __syncthreads();

        // ---- thread-local quarter-row reduction (conflict-free: stride 25) ----
        const float* rp = &sbuf[b][tid * 25];
        float m   = rp[0];
        int   idx = q * 25;
        int   cnt = (m > -4.0f);
        #pragma unroll
        for (int i = 1; i < 25; i++) {
            float x = rp[i];
            cnt += (x > -4.0f);
            if (x > m) { m = x; idx = q * 25 + i; }   // strict > keeps first occurrence
        }

        // ---- merge 4 quarters: (value desc, index asc) ----
        #pragma unroll
        for (int off = 1; off <= 2; off <<= 1) {
            float om = __shfl_xor_sync(FULLM, m,   off);
            int   oi = __shfl_xor_sync(FULLM, idx, off);
            int   oc = __shfl_xor_sync(FULLM, cnt, off);
            cnt += oc;
            if (om > m || (om == m && oi < idx)) { m = om; idx = oi; }
        }

        int row = tile * TILE_ROWS + (tid >> 2);
        if (q == 0 && row < n_rows) {
            // certification: cnt>=2 => a 2nd element > -4; with m < 8 that 2nd
            // element > m-12, and -16 < m < 8 => log(sumexp) >= log(1+e^-12)
            // = 6.1e-6 > ulp(m)/2 => max logprob strictly < 0 => never equals
            // an integer label => acc = 0. Exact; fallback otherwise.
            bool good = (cnt >= 2) && (m < 8.0f) && (m > -16.0f);
            if (!good) {   // statistically never taken
                const float* rb = &sbuf[b][(tid >> 2) * C_CLASSES];
                float sv = 0.0f;
                for (int i = 0; i < C_CLASSES; i++) sv += expf(rb[i] - m);
                float pred = m - (m + logf(sv));
                if (pred == (float)labels[row]) atomicAdd(&s_acc[idx], 1);
            }
            atomicAdd(&s_cnt[idx], 1);
        }
        __syncthreads();   // all reads of buf b done before it is re-filled
    }
    asm volatile("cp.async.wait_group 0;" ::: "memory");

    // ---- flush block histogram to global ----
    __syncthreads();
    for (int i = tid; i < C_CLASSES; i += THREADS) {
        int c = s_cnt[i]; if (c) atomicAdd(&g_cnt[i], c);
        int a = s_acc[i]; if (a) atomicAdd(&g_acc[i], a);
    }
    __threadfence();
    __syncthreads();

    if (tid == 0) {
        unsigned rank = atomicAdd(&g_done, 1u);
        s_last = (rank == gridDim.x - 1);
    }
    __syncthreads();
    if (!s_last) return;

    // ================= finalize (last block only; alias tile SMEM) =========
    float (*s_coef)[NB + 1] = reinterpret_cast<float(*)[NB + 1]>(&sbuf[0][0]); // 1600 f
    int*   s_c2   = reinterpret_cast<int*>(&sbuf[0][1600]);
    int*   s_a2   = reinterpret_cast<int*>(&sbuf[0][1728]);
    float* s_sum  = &sbuf[0][1856];
    float* s_conf = &sbuf[0][1872];
    float* s_accs = &sbuf[0][1888];

    int t = tid;
    if (t < C_CLASSES) {
        int cnt = __ldcg(&g_cnt[t]);
        int ac  = __ldcg(&g_acc[t]);
        s_c2[t] = cnt;
        s_a2[t] = ac;
        float cf = (float)t;
        float d[NB];
        float dmax = __int_as_float(0xff800000);
        #pragma unroll
        for (int jj = 0; jj < NB; jj++) {
            float aj = (float)((2 * jj + 1) / 30.0);
            float tt = cf - aj;
            d[jj] = -(tt * tt) / 0.01f;
            dmax = fmaxf(dmax, d[jj]);
        }
        float denom = 0.0f;
        #pragma unroll
        for (int jj = 0; jj < NB; jj++) denom += expf(d[jj] - dmax);
        #pragma unroll
        for (int jj = 0; jj < NB; jj++) s_coef[t][jj] = expf(d[jj] - dmax) / denom;
        g_cnt[t] = 0;     // reset for next graph replay
        g_acc[t] = 0;
    }
    if (t == 0) g_done = 0;
    __syncthreads();

    if (t < NB) {
        float sum_c = 0.0f, sum_cc = 0.0f, sum_a = 0.0f;
        for (int c = 0; c < C_CLASSES; c++) {
            int cnt = s_c2[c];
            int ac  = s_a2[c];
            if ((cnt | ac) == 0) continue;
            float coeff = s_coef[c][t];
            float fcnt  = (float)cnt;   // exact: cnt < 2^24
            float cf    = (float)c;
            sum_c  += fcnt * coeff;
            sum_cc += fcnt * cf * coeff;
            sum_a  += (float)ac * coeff;
        }
        s_sum[t]  = sum_c;
        s_conf[t] = sum_cc;
        s_accs[t] = sum_a;
    }
    __syncthreads();

    if (t == 0) {
        float tot = 0.0f;
        #pragma unroll
        for (int jj = 0; jj < NB; jj++) tot += fabsf(s_sum[jj]);
        float wden = fmaxf(tot, 1e-5f);
        float acc2 = 0.0f;
        #pragma unroll
        for (int jj = 0; jj < NB; jj++) {
            float den = fmaxf(s_sum[jj], 1e-5f);
            float bc  = s_conf[jj] / den;
            float ba  = s_accs[jj] / den;
            float w   = s_sum[jj] / wden;
            float df  = bc - ba;
            acc2 += df * df * w;
        }
        out[0] = sqrtf(acc2);
    }
}

extern "C" void kernel_launch(void* const* d_in, const int* in_sizes, int n_in,
                              void* d_out, int out_size) {
    const float*     logits = (const float*)d_in[0];
    const long long* labels = (const long long*)d_in[1];
    float*           out    = (float*)d_out;
    int n_rows = in_sizes[1];  // labels count = N

    // 16384 tiles / 1024 blocks = 16 tiles each, exact; 8 blocks/SM resident
    fused_kernel<<<1024, THREADS>>>(logits, labels, n_rows, out);
}